// round 3
// baseline (speedup 1.0000x reference)
#include <cuda_runtime.h>
#include <cuda_bf16.h>
#include <cstdint>
#include <cstddef>

// Problem constants
#define TT   2048      // sequence length
#define EE   300       // embedding dim
#define HH   512       // hidden dim

// ---------------- device scratch (allocation-free rule: __device__ globals) -------
__device__ float g_gx[(size_t)4 * TT * 2048];   // [dir*2+sent][t][4H]  (64 MB)
__device__ float g_h[2][2][2][HH];              // [parity][dir][sent][H]

__device__ __forceinline__ float sigf(float x) { return 1.f / (1.f + expf(-x)); }

// ---------------- phase 1: gx = emb[sent] @ w_ih^T + (b_ih + b_hh) ----------------
// grid: (32 t-tiles, 64 r-tiles over 4096 rows [dir-major], 2 sentences), 256 thr
__global__ void gemm_gx_kernel(const int* __restrict__ sA, const int* __restrict__ sB,
                               const float* __restrict__ emb,
                               const float* __restrict__ w_ih,
                               const float* __restrict__ b_ih,
                               const float* __restrict__ b_hh)
{
    const int t0 = blockIdx.x * 64;
    const int r0 = blockIdx.y * 64;          // global row in [0,4096)
    const int s  = blockIdx.z;
    const int* sent = s ? sB : sA;
    const int d = r0 >> 11;                  // direction from row block

    __shared__ float As[32][65];             // [k][t]
    __shared__ float Bs[32][65];             // [k][r]
    __shared__ int   toks[64];

    const int tid = threadIdx.x;
    const int ty = tid >> 4, tx = tid & 15;

    if (tid < 64) toks[tid] = sent[t0 + tid];
    __syncthreads();

    float acc[4][4] = {};

    for (int k0 = 0; k0 < EE; k0 += 32) {
#pragma unroll
        for (int m = 0; m < 8; ++m) {
            int idx = tid + m * 256;
            int tt = idx >> 5, kk = idx & 31;
            int k = k0 + kk;
            As[kk][tt] = (k < EE) ? emb[(size_t)toks[tt] * EE + k] : 0.f;
        }
#pragma unroll
        for (int m = 0; m < 8; ++m) {
            int idx = tid + m * 256;
            int rr = idx >> 5, kk = idx & 31;
            int k = k0 + kk;
            Bs[kk][rr] = (k < EE) ? w_ih[(size_t)(r0 + rr) * EE + k] : 0.f;
        }
        __syncthreads();
#pragma unroll
        for (int kk = 0; kk < 32; ++kk) {
            float a0 = As[kk][ty * 4 + 0], a1 = As[kk][ty * 4 + 1];
            float a2 = As[kk][ty * 4 + 2], a3 = As[kk][ty * 4 + 3];
            float b0 = Bs[kk][tx * 4 + 0], b1 = Bs[kk][tx * 4 + 1];
            float b2 = Bs[kk][tx * 4 + 2], b3 = Bs[kk][tx * 4 + 3];
            acc[0][0] += a0 * b0; acc[0][1] += a0 * b1; acc[0][2] += a0 * b2; acc[0][3] += a0 * b3;
            acc[1][0] += a1 * b0; acc[1][1] += a1 * b1; acc[1][2] += a1 * b2; acc[1][3] += a1 * b3;
            acc[2][0] += a2 * b0; acc[2][1] += a2 * b1; acc[2][2] += a2 * b2; acc[2][3] += a2 * b3;
            acc[3][0] += a3 * b0; acc[3][1] += a3 * b1; acc[3][2] += a3 * b2; acc[3][3] += a3 * b3;
        }
        __syncthreads();
    }

#pragma unroll
    for (int i = 0; i < 4; ++i) {
        int t = t0 + ty * 4 + i;
        int tstore = d ? (TT - 1 - t) : t;   // bwd chain consumes reversed sequence
        size_t rowbase = (((size_t)(d * 2 + s)) * TT + tstore) * 2048;
#pragma unroll
        for (int j = 0; j < 4; ++j) {
            int r = r0 + tx * 4 + j;         // 0..4095; b_ih/b_hh are flat [2][2048]
            g_gx[rowbase + (r & 2047)] = acc[i][j] + b_ih[r] + b_hh[r];
        }
    }
}

// ---------------- phase 2: persistent cluster LSTM ------------------------------
// 2 clusters (one per direction) x CSZ CTAs x 512 threads. cluster.sync() is the
// per-timestep barrier (hardware co-scheduling guarantee -> deadlock-free).
// CTA `rank` owns hidden units [rank*UPC, (rank+1)*UPC) for BOTH sentences.
template <int CSZ>
__global__ void __launch_bounds__(512, 1)
lstm_cluster_kernel(const float* __restrict__ w_hh)
{
    constexpr int UPC  = HH / CSZ;       // units per CTA
    constexpr int ROWS = 4 * UPC;        // gate-rows per CTA
    constexpr int NW   = 16;             // warps per CTA
    constexpr int RPW  = ROWS / NW;      // rows per warp

    __shared__ float h_s[2][HH];         // [sent][H] previous hidden (this dir)
    __shared__ float gates_s[2][ROWS];   // [sent][gate*UPC + u]
    __shared__ float c_s[2][UPC];        // cell state, CTA-local, persistent

    const int tid  = threadIdx.x;
    const int lane = tid & 31;
    const int wid  = tid >> 5;
    const int dir  = blockIdx.x / CSZ;   // cluster id (clusters are contiguous in x)
    const int rank = blockIdx.x % CSZ;   // rank within cluster
    const int ku   = rank * UPC;         // first unit owned by this CTA

    // zero initial state
    for (int i = tid; i < 2 * HH; i += 512) h_s[0][i] = 0.f;
    for (int i = tid; i < 2 * UPC; i += 512) c_s[0][i] = 0.f;
    __syncthreads();

    // precompute weight row pointers for this warp's RPW rows (constant over t)
    const float* wbase = w_hh + (size_t)dir * 2048 * HH;
    const float4* wrp[RPW];
#pragma unroll
    for (int j = 0; j < RPW; ++j) {
        int r_local = wid * RPW + j;          // [0, ROWS)
        int gate = r_local / UPC;
        int u_l  = r_local % UPC;
        wrp[j] = reinterpret_cast<const float4*>(
            wbase + ((size_t)gate * HH + ku + u_l) * HH);
    }

    // pointwise-update thread bases
    const int uu = tid >> 1;                  // unit local index
    const int ss = tid & 1;                   // sentence
    const float* pgx = g_gx + ((size_t)(dir * 2 + ss) * TT) * 2048 + (ku + uu);

    const float4* hA4 = reinterpret_cast<const float4*>(h_s[0]);
    const float4* hB4 = reinterpret_cast<const float4*>(h_s[1]);

    for (int t = 0; t < TT; ++t) {
        // ---- matvec: each warp computes RPW gate-rows for both sentences ----
        float4 ha[4], hb[4];
#pragma unroll
        for (int i = 0; i < 4; ++i) {
            ha[i] = hA4[lane + 32 * i];
            hb[i] = hB4[lane + 32 * i];
        }
        float accA[RPW], accB[RPW];
#pragma unroll
        for (int j = 0; j < RPW; ++j) { accA[j] = 0.f; accB[j] = 0.f; }
#pragma unroll
        for (int j = 0; j < RPW; ++j) {
            const float4* wr = wrp[j];
#pragma unroll
            for (int i = 0; i < 4; ++i) {
                float4 wv = wr[lane + 32 * i];
                accA[j] += wv.x * ha[i].x + wv.y * ha[i].y + wv.z * ha[i].z + wv.w * ha[i].w;
                accB[j] += wv.x * hb[i].x + wv.y * hb[i].y + wv.z * hb[i].z + wv.w * hb[i].w;
            }
        }
#pragma unroll
        for (int off = 16; off; off >>= 1) {
#pragma unroll
            for (int j = 0; j < RPW; ++j) {
                accA[j] += __shfl_xor_sync(0xffffffffu, accA[j], off);
                accB[j] += __shfl_xor_sync(0xffffffffu, accB[j], off);
            }
        }
        if (lane == 0) {
#pragma unroll
            for (int j = 0; j < RPW; ++j) {
                int r_local = wid * RPW + j;
                gates_s[0][r_local] = accA[j];
                gates_s[1][r_local] = accB[j];
            }
        }
        __syncthreads();

        // ---- pointwise cell update: 2*UPC threads, one (unit, sentence) each ----
        if (tid < 2 * UPC) {
            const float* px = pgx + (size_t)t * 2048;
            float g0 = gates_s[ss][0 * UPC + uu] + px[0 * HH];
            float g1 = gates_s[ss][1 * UPC + uu] + px[1 * HH];
            float g2 = gates_s[ss][2 * UPC + uu] + px[2 * HH];
            float g3 = gates_s[ss][3 * UPC + uu] + px[3 * HH];
            float c = sigf(g1) * c_s[ss][uu] + sigf(g0) * tanhf(g2);
            c_s[ss][uu] = c;
            g_h[(t + 1) & 1][dir][ss][ku + uu] = sigf(g3) * tanhf(c);
        }

        // ---- cluster barrier: release h stores, acquire peers' h ----
        asm volatile("barrier.cluster.arrive.aligned;" ::: "memory");
        asm volatile("barrier.cluster.wait.aligned;"   ::: "memory");

        // ---- reload full h (both sentences) for this direction ----
        if (tid < 256) {
            const float4* hg4 = reinterpret_cast<const float4*>(&g_h[(t + 1) & 1][dir][0][0]);
            reinterpret_cast<float4*>(h_s[0])[tid] = hg4[tid];
        }
        __syncthreads();
    }
}

// ---------------- phase 3: bi-mix + double linear + tanh + out + sigmoid ----------
__global__ void head_kernel(const float* __restrict__ bi_w, const float* __restrict__ bi_b,
                            const float* __restrict__ blA, const float* __restrict__ blB,
                            const float* __restrict__ bl_b,
                            const float* __restrict__ out_w, const float* __restrict__ out_b,
                            float* __restrict__ out)
{
    __shared__ float hA[HH], hB[HH];
    __shared__ float red[16];
    const int j = threadIdx.x;   // 512 threads
    const float w0 = bi_w[0], w1 = bi_w[1], bb = bi_b[0];

    // final h lives in parity buffer 0 (t=2047 writes (t+1)&1 == 0)
    hA[j] = w0 * g_h[0][0][0][j] + w1 * g_h[0][1][0][j] + bb;
    hB[j] = w0 * g_h[0][0][1][j] + w1 * g_h[0][1][1][j] + bb;
    __syncthreads();

    float acc = bl_b[j];
#pragma unroll 4
    for (int i = 0; i < HH; ++i)
        acc += hA[i] * blA[(size_t)i * HH + j] + hB[i] * blB[(size_t)i * HH + j];

    float v = tanhf(acc) * out_w[j];
#pragma unroll
    for (int off = 16; off; off >>= 1) v += __shfl_xor_sync(0xffffffffu, v, off);
    if ((j & 31) == 0) red[j >> 5] = v;
    __syncthreads();
    if (j < 16) {
        float r = red[j];
#pragma unroll
        for (int off = 8; off; off >>= 1) r += __shfl_xor_sync(0x0000ffffu, r, off);
        if (j == 0) out[0] = 1.f / (1.f + expf(-(r + out_b[0])));
    }
}

// ---------------- launch ----------------------------------------------------------
extern "C" void kernel_launch(void* const* d_in, const int* in_sizes, int n_in,
                              void* d_out, int out_size)
{
    (void)in_sizes; (void)n_in; (void)out_size;
    const int*   sentA = (const int*)d_in[0];
    const int*   sentB = (const int*)d_in[1];
    // d_in[2] = hidden (unused by forward)
    const float* emb   = (const float*)d_in[3];
    const float* w_ih  = (const float*)d_in[4];
    const float* w_hh  = (const float*)d_in[5];
    const float* b_ih  = (const float*)d_in[6];
    const float* b_hh  = (const float*)d_in[7];
    const float* bi_w  = (const float*)d_in[8];
    const float* bi_b  = (const float*)d_in[9];
    const float* blA   = (const float*)d_in[10];
    const float* blB   = (const float*)d_in[11];
    const float* bl_b  = (const float*)d_in[12];
    const float* out_w = (const float*)d_in[13];
    const float* out_b = (const float*)d_in[14];
    float* out = (float*)d_out;

    gemm_gx_kernel<<<dim3(32, 64, 2), 256>>>(sentA, sentB, emb, w_ih, b_ih, b_hh);

    // cluster-16 (non-portable) with validated fallback to cluster-8
    cudaFuncSetAttribute(lstm_cluster_kernel<16>,
                         cudaFuncAttributeNonPortableClusterSizeAllowed, 1);

    cudaLaunchConfig_t cfg = {};
    cfg.blockDim = dim3(512, 1, 1);
    cfg.dynamicSmemBytes = 0;
    cfg.stream = 0;
    cudaLaunchAttribute attr[1];
    attr[0].id = cudaLaunchAttributeClusterDimension;
    cfg.attrs = attr;
    cfg.numAttrs = 1;

    cfg.gridDim = dim3(2 * 16, 1, 1);
    attr[0].val.clusterDim.x = 16; attr[0].val.clusterDim.y = 1; attr[0].val.clusterDim.z = 1;

    int nclusters = 0;
    cudaError_t e = cudaOccupancyMaxActiveClusters(&nclusters, lstm_cluster_kernel<16>, &cfg);
    if (e == cudaSuccess && nclusters >= 1) {
        cudaLaunchKernelEx(&cfg, lstm_cluster_kernel<16>, w_hh);
    } else {
        (void)cudaGetLastError();  // clear sticky error from the query path
        cfg.gridDim = dim3(2 * 8, 1, 1);
        attr[0].val.clusterDim.x = 8;
        cudaLaunchKernelEx(&cfg, lstm_cluster_kernel<8>, w_hh);
    }

    head_kernel<<<1, 512>>>(bi_w, bi_b, blA, blB, bl_b, out_w, out_b, out);
}